// round 11
// baseline (speedup 1.0000x reference)
#include <cuda_runtime.h>
#include <math.h>

#define BB   4
#define HWD  16384
#define SPPX 3
#define CCH  64
#define NG   (BB*HWD*SPPX)      /* 196608 gaussians */
#define GPB  128                /* gaussians per block */
#define THR  256                /* threads per block: 2 per gaussian */
#define NGB  (HWD*SPPX)         /* gaussians per batch = 49152 */
#define NHW  44                 /* hw rows per block tile */
#define FTS  68                 /* feat tile row stride (16B aligned) */

/* output layout (floats): means|cov|sh|opa|feat|scales|rot */
#define OFF_MEANS ((size_t)0)
#define OFF_COV   ((size_t)3*NG)
#define OFF_SH    ((size_t)12*NG)
#define OFF_OPA   ((size_t)87*NG)
#define OFF_FEAT  ((size_t)88*NG)
#define OFF_SCL   ((size_t)152*NG)
#define OFF_ROT   ((size_t)155*NG)

static __device__ const int d_LOFF[5] = {0,1,10,35,84};

__device__ float g_D[BB*165];   /* Wigner D per batch, concat l=0..4 */
__device__ float g_cb[BB*24];   /* per-batch consts: R(9) o(3) Kinv(9) mult */

/* ------------------------------------------------------------------ */
__device__ __forceinline__ void wmmf(const float* A, const float* B, float* C,
                                     int n, int lane){
    for (int idx=lane; idx<n*n; idx+=32){
        int r=idx/n, c=idx-r*n;
        float s=0.f;
        for (int k=0;k<n;k++) s += A[r*n+k]*B[k*n+c];
        C[idx]=s;
    }
}

/* Taylor expm (9 terms, threshold 1.0, scaling & squaring) */
__device__ void wexpmf(float theta, const float* G, int n, int lane,
                       float* M, float* P, float* T){
    const int n2=n*n;
    for (int i=lane;i<n2;i+=32) M[i]=theta*G[i];
    __syncwarp();
    int s=0;
    if (lane==0){
        float nm=0.f;
        for (int r=0;r<n;r++){
            float rs=0.f;
            for (int c=0;c<n;c++) rs += fabsf(M[r*n+c]);
            nm = fmaxf(nm, rs);
        }
        while (nm > 1.0f){ nm*=0.5f; s++; }
    }
    s = __shfl_sync(0xffffffffu, s, 0);
    float scl = ldexpf(1.0f, -s);
    for (int i=lane;i<n2;i+=32) M[i]*=scl;
    __syncwarp();
    for (int i=lane;i<n2;i+=32) P[i] = ((i/n)==(i%n)) ? 1.0f : 0.0f;
    __syncwarp();
    for (int k=9;k>=1;k--){
        wmmf(M,P,T,n,lane); __syncwarp();
        float ik = 1.0f/(float)k;
        for (int i=lane;i<n2;i+=32)
            P[i] = T[i]*ik + (((i/n)==(i%n)) ? 1.0f : 0.0f);
        __syncwarp();
    }
    for (int it=0; it<s; it++){
        wmmf(P,P,T,n,lane); __syncwarp();
        for (int i=lane;i<n2;i+=32) P[i]=T[i];
        __syncwarp();
    }
}

__device__ __forceinline__ int read_dim(const void* p, int defv){
    if (!p) return defv;
    int iv = *(const int*)p;
    if (iv>=1 && iv<=(1<<20)) return iv;
    float fv = *(const float*)p;
    if (fv>=1.0f && fv<=1048576.0f) return (int)(fv+0.5f);
    return defv;
}

/* ------------------------------------------------------------------ */
/* Setup kernel: grid = BB*5 (b,l), block = 32.                       */
/* EA = e^{alpha X1}, EC = e^{gamma X1} closed form via               */
/*   e^{a X1} = Q^H diag(e^{i m a}) Q. EB = e^{-beta X0} short Taylor. */
__global__ void setup_kernel(const float* __restrict__ ext,
                             const float* __restrict__ intr,
                             const void* ph, const void* pw){
    const int b = blockIdx.x/5, l = blockIdx.x%5;
    const int n = 2*l+1, n2 = n*n;
    const int lane = threadIdx.x;
    __shared__ float Qre[81],Qim[81],Sre[81],Tre[81],Tim[81];
    __shared__ float Gx[81],EA[81],EB[81],EC[81],M[81],P[81],W[81];
    __shared__ float cs[9], sn[9], cg[9], sg2[9];

    for (int i=lane;i<n2;i+=32){ Qre[i]=0.f; Qim[i]=0.f; }
    __syncwarp();
    if (lane==0){
        const float is2 = 0.70710678118654752440f;
        for (int m=-l;m<0;m++){
            Qre[(l+m)*n+(l-m)] = is2;
            Qim[(l+m)*n+(l+m)] = -is2;
        }
        Qre[l*n+l] = 1.0f;
        for (int m=1;m<=l;m++){
            float sgn = (m&1)? -1.0f : 1.0f;
            Qre[(l+m)*n+(l+m)] = sgn*is2;
            Qim[(l+m)*n+(l-m)] = sgn*is2;
        }
    }
    __syncwarp();
    {
        float cr,ci;
        switch (l&3){
            case 0: cr=1;  ci=0;  break;
            case 1: cr=0;  ci=-1; break;
            case 2: cr=-1; ci=0;  break;
            default:cr=0;  ci=1;  break;
        }
        for (int i=lane;i<n2;i+=32){
            float re=Qre[i], im=Qim[i];
            Qre[i]=re*cr-im*ci; Qim[i]=re*ci+im*cr;
        }
    }
    __syncwarp();

    /* Gx = Re(Q^H X0 Q), X0 real antisymmetric */
    for (int i=lane;i<n2;i+=32) Sre[i]=0.f;
    __syncwarp();
    if (lane==0){
        float jj=(float)l;
        for (int i=0;i<n-1;i++){
            float m = -jj + (float)i;
            float sq = sqrtf(jj*(jj+1.0f) - m*(m+1.0f));
            Sre[(i+1)*n+i] = -0.5f*sq; Sre[i*n+(i+1)] = 0.5f*sq;
        }
    }
    __syncwarp();
    for (int idx=lane; idx<n2; idx+=32){
        int r=idx/n, c=idx-r*n;
        float sre=0.f, sim=0.f;
        for (int k=0;k<n;k++){
            float xr=Sre[r*n+k];
            sre += xr*Qre[k*n+c]; sim += xr*Qim[k*n+c];
        }
        Tre[idx]=sre; Tim[idx]=sim;
    }
    __syncwarp();
    for (int idx=lane; idx<n2; idx+=32){
        int r=idx/n, c=idx-r*n;
        float s=0.f;
        for (int k=0;k<n;k++)
            s += Qre[k*n+r]*Tre[k*n+c] + Qim[k*n+r]*Tim[k*n+c];
        Gx[idx] = s;
    }
    __syncwarp();

    /* angles */
    float al=0.f, be=0.f, ga=0.f;
    if (lane==0){
        float R[3][3];
        for (int r=0;r<3;r++) for (int c=0;c<3;c++) R[r][c] = ext[b*16+r*4+c];
        float x0=R[0][1], x1=R[1][1], x2=R[2][1];
        float inv = 1.0f/sqrtf(x0*x0+x1*x1+x2*x2);
        x0*=inv; x1*=inv; x2*=inv;
        be = acosf(fminf(1.0f, fmaxf(-1.0f, x1)));
        al = atan2f(x0, x2);
        float ca=cosf(al), sa=sinf(al);
        float Rp00 = ca*R[0][0] - sa*R[2][0];
        float Rp02 = ca*R[0][2] - sa*R[2][2];
        ga = atan2f(Rp02, Rp00);
    }
    al = __shfl_sync(0xffffffffu, al, 0);
    be = __shfl_sync(0xffffffffu, be, 0);
    ga = __shfl_sync(0xffffffffu, ga, 0);

    if (lane < n){
        float m = (float)(lane - l);
        cs[lane] = cosf(m*al);  sn[lane]  = sinf(m*al);
        cg[lane] = cosf(m*ga);  sg2[lane] = sinf(m*ga);
    }
    __syncwarp();
    for (int idx=lane; idx<n2; idx+=32){
        int r=idx/n, c=idx-r*n;
        float sa_=0.f, sc_=0.f;
        for (int k=0;k<n;k++){
            float ar=Qre[k*n+r], ai=Qim[k*n+r];
            float br=Qre[k*n+c], bi=Qim[k*n+c];
            float pre = ar*br + ai*bi;
            float pim = ar*bi - ai*br;
            sa_ += pre*cs[k] - pim*sn[k];
            sc_ += pre*cg[k] - pim*sg2[k];
        }
        EA[idx]=sa_; EC[idx]=sc_;
    }
    __syncwarp();

    wexpmf(-be, Gx, n, lane, M,P,W);
    for (int i=lane;i<n2;i+=32) EB[i]=P[i];
    __syncwarp();

    wmmf(EB,EC,W,n,lane); __syncwarp();
    wmmf(EA,W,M,n,lane);  __syncwarp();
    for (int i=lane;i<n2;i+=32)
        g_D[b*165 + d_LOFF[l] + i] = M[i];

    if (l==0 && lane==0){
        float K[3][3];
        for (int r=0;r<3;r++) for (int c=0;c<3;c++) K[r][c]=intr[b*9+r*3+c];
        float det = K[0][0]*(K[1][1]*K[2][2]-K[1][2]*K[2][1])
                  - K[0][1]*(K[1][0]*K[2][2]-K[1][2]*K[2][0])
                  + K[0][2]*(K[1][0]*K[2][1]-K[1][1]*K[2][0]);
        float id = 1.0f/det;
        float Ki[3][3];
        Ki[0][0]=(K[1][1]*K[2][2]-K[1][2]*K[2][1])*id;
        Ki[0][1]=(K[0][2]*K[2][1]-K[0][1]*K[2][2])*id;
        Ki[0][2]=(K[0][1]*K[1][2]-K[0][2]*K[1][1])*id;
        Ki[1][0]=(K[1][2]*K[2][0]-K[1][0]*K[2][2])*id;
        Ki[1][1]=(K[0][0]*K[2][2]-K[0][2]*K[2][0])*id;
        Ki[1][2]=(K[0][2]*K[1][0]-K[0][0]*K[1][2])*id;
        Ki[2][0]=(K[1][0]*K[2][1]-K[1][1]*K[2][0])*id;
        Ki[2][1]=(K[0][1]*K[2][0]-K[0][0]*K[2][1])*id;
        Ki[2][2]=(K[0][0]*K[1][1]-K[0][1]*K[1][0])*id;

        int Hh = read_dim(ph, 128);
        int Ww = read_dim(pw, 128);
        float psx = 1.0f/(float)Ww, psy = 1.0f/(float)Hh;
        float d2  = K[0][0]*K[1][1]-K[0][1]*K[1][0];
        float v0  = ( K[1][1]*psx - K[0][1]*psy)/d2;
        float v1  = (-K[1][0]*psx + K[0][0]*psy)/d2;
        float mult = 0.1f*(v0+v1);

        float* cb = g_cb + b*24;
        for (int r=0;r<3;r++) for (int c=0;c<3;c++) cb[r*3+c]=ext[b*16+r*4+c];
        for (int r=0;r<3;r++) cb[9+r]=ext[b*16+r*4+3];
        for (int r=0;r<3;r++) for (int c=0;c<3;c++) cb[12+r*3+c]=Ki[r][c];
        cb[21]=mult;
    }
}

/* ------------------------------------------------------------------ */
/* Main kernel: 2 threads per gaussian (sub=tid&1), 256 threads/CTA.  */
__global__ void __launch_bounds__(THR, 4)
gauss_kernel(const float* __restrict__ coords, const float* __restrict__ depths,
             const float* __restrict__ opac,   const float* __restrict__ raw,
             const float* __restrict__ gf,     float* __restrict__ out){
    extern __shared__ float sm[];
    float* s_in = sm;                  /* GPB*83 (odd stride, conflict-free) */
    float* s_ft = s_in + GPB*83;       /* NHW*FTS feat tile [hw][c]          */
    float* s_D  = s_ft + NHW*FTS;      /* 165 (mask folded in)               */
    float* s_cb = s_D  + 165;          /* 24                                 */

    const int tid  = threadIdx.x;
    const int g0   = blockIdx.x*GPB;
    const int b    = g0/NGB;
    const int idx0 = g0 - b*NGB;
    const int hw0  = idx0/3;

    {
        const float MSK[5] = {1.0f, 0.025f, 0.00625f, 0.0015625f, 0.000390625f};
        for (int i=tid;i<165;i+=THR){
            int l = (i>=84)?4:(i>=35)?3:(i>=10)?2:(i>=1)?1:0;
            s_D[i] = g_D[b*165+i]*MSK[l];
        }
    }
    if (tid < 24) s_cb[tid] = g_cb[b*24+tid];

    /* stage feat tile: [hw][c], coalesced gmem reads */
    {
        const float* gfb = gf + (size_t)b*CCH*HWD;
        #pragma unroll 4
        for (int i=tid; i<CCH*NHW; i+=THR){
            int c = i/NHW, j = i - c*NHW;
            int hwrow = hw0 + j;
            float v = (hwrow < HWD) ? gfb[(size_t)c*HWD + hwrow] : 0.f;
            s_ft[j*FTS + c] = v;
        }
    }

    /* stage raw_gaussians: coalesced float4 loads -> padded rows */
    {
        const float4* src = reinterpret_cast<const float4*>(raw + (size_t)g0*82);
        #pragma unroll 4
        for (int i=tid; i<GPB*82/4; i+=THR){
            float4 v = src[i];
            int lin = i*4;
            float vv[4] = {v.x, v.y, v.z, v.w};
            #pragma unroll
            for (int w=0; w<4; w++){
                int t = (lin+w)/82;
                int j = (lin+w) - t*82;
                s_in[t*83 + j] = vv[w];
            }
        }
    }
    __syncthreads();

    const int gl  = tid>>1;
    const int sub = tid&1;
    const int g   = g0 + gl;
    float* in = s_in + gl*83;
    const float depth = depths[g];
    const float mult  = s_cb[21];

    /* both pair-threads compute scales (cheap; needed by both halves) */
    float sc[3];
    #pragma unroll
    for (int i=0;i<3;i++){
        float x = in[i];
        float sig = 1.0f/(1.0f+expf(-x));
        sc[i] = (0.5f + 14.5f*sig) * depth * mult;
    }

    if (sub==0){
        out[OFF_OPA + g] = opac[g];
        const float2 uv = reinterpret_cast<const float2*>(coords)[g];
        float dx = s_cb[12]*uv.x + s_cb[13]*uv.y + s_cb[14];
        float dy = s_cb[15]*uv.x + s_cb[16]*uv.y + s_cb[17];
        float dz = s_cb[18]*uv.x + s_cb[19]*uv.y + s_cb[20];
        float dn = 1.0f/sqrtf(dx*dx+dy*dy+dz*dz);
        dx*=dn; dy*=dn; dz*=dn;
        float wx = s_cb[0]*dx + s_cb[1]*dy + s_cb[2]*dz;
        float wy = s_cb[3]*dx + s_cb[4]*dy + s_cb[5]*dz;
        float wz = s_cb[6]*dx + s_cb[7]*dy + s_cb[8]*dz;
        float* mo = out + OFF_MEANS + (size_t)g*3;
        mo[0] = s_cb[9]  + wx*depth;
        mo[1] = s_cb[10] + wy*depth;
        mo[2] = s_cb[11] + wz*depth;
        /* stash scales (pair partner already consumed in[0..2] above) */
        in[0]=sc[0]; in[1]=sc[1]; in[2]=sc[2];
    } else {
        float q0=in[3], q1=in[4], q2=in[5], q3=in[6];
        float nq = sqrtf(q0*q0+q1*q1+q2*q2+q3*q3);
        float invq = 1.0f/(nq + 1e-8f);
        q0*=invq; q1*=invq; q2*=invq; q3*=invq;
        float ss = 2.0f/(q0*q0+q1*q1+q2*q2+q3*q3);
        const float r=q0, ii=q1, jj=q2, kk=q3;
        float R00=1.f-ss*(jj*jj+kk*kk), R01=ss*(ii*jj-kk*r), R02=ss*(ii*kk+jj*r);
        float R10=ss*(ii*jj+kk*r), R11=1.f-ss*(ii*ii+kk*kk), R12=ss*(jj*kk-ii*r);
        float R20=ss*(ii*kk-jj*r), R21=ss*(jj*kk+ii*r), R22=1.f-ss*(ii*ii+jj*jj);
        float v0=sc[0]*sc[0], v1=sc[1]*sc[1], v2=sc[2]*sc[2];
        float c00=R00*R00*v0+R01*R01*v1+R02*R02*v2;
        float c01=R00*R10*v0+R01*R11*v1+R02*R12*v2;
        float c02=R00*R20*v0+R01*R21*v1+R02*R22*v2;
        float c11=R10*R10*v0+R11*R11*v1+R12*R12*v2;
        float c12=R10*R20*v0+R11*R21*v1+R12*R22*v2;
        float c22=R20*R20*v0+R21*R21*v1+R22*R22*v2;
        float* co = out + OFF_COV + (size_t)g*9;
        co[0]=c00; co[1]=c01; co[2]=c02;
        co[3]=c01; co[4]=c11; co[5]=c12;
        co[6]=c02; co[7]=c12; co[8]=c22;
        /* stash normalized quat */
        in[3]=q0; in[4]=q1; in[5]=q2; in[6]=q3;
    }

    /* SH rotation IN PLACE, rows split across the thread pair.       */
    /* mask is folded into s_D. __syncwarp() separates the t[] loads  */
    /* from the in-place stores (ITS safety).                         */
    {
        float* shp = in + 7;
        const float d0 = s_D[0];
        if (sub==0){ shp[0]*=d0; shp[25]*=d0; }
        else       { shp[50]*=d0; }
        const int LOFFc[5] = {0,1,10,35,84};
        #pragma unroll
        for (int l=1;l<5;l++){
            const int n = 2*l+1, off = l*l;
            const float* D = s_D + LOFFc[l];
            #pragma unroll
            for (int ch=0; ch<3; ch++){
                float* p = shp + ch*25 + off;
                float t[9];
                #pragma unroll
                for (int j=0;j<n;j++) t[j] = p[j];
                __syncwarp();
                for (int i=sub; i<n; i+=2){
                    float a = 0.f;
                    #pragma unroll
                    for (int j=0;j<n;j++) a += D[i*n+j]*t[j];
                    p[i] = a;
                }
                __syncwarp();
            }
        }
    }
    __syncthreads();

    /* coalesced float4 flush */
    {
        /* SH */
        float4* d4 = (float4*)(out + OFF_SH + (size_t)g0*75);
        #pragma unroll 4
        for (int i=tid; i<GPB*75/4; i+=THR){
            int lin = i*4; float vv[4];
            #pragma unroll
            for (int w=0;w<4;w++){
                int idx=lin+w, t=idx/75, j=idx-t*75;
                vv[w] = s_in[t*83+7+j];
            }
            d4[i] = make_float4(vv[0],vv[1],vv[2],vv[3]);
        }
        /* features: LDS128 from [hw][c] tile */
        d4 = (float4*)(out + OFF_FEAT + (size_t)g0*64);
        #pragma unroll 4
        for (int i=tid; i<GPB*64/4; i+=THR){
            int lin = i*4;
            int gg  = lin>>6;
            int c0  = lin & 63;
            int hwl = (idx0+gg)/3 - hw0;
            d4[i] = *reinterpret_cast<const float4*>(&s_ft[hwl*FTS + c0]);
        }
        /* scales */
        d4 = (float4*)(out + OFF_SCL + (size_t)g0*3);
        for (int i=tid; i<GPB*3/4; i+=THR){
            int lin=i*4; float vv[4];
            #pragma unroll
            for (int w=0;w<4;w++){
                int idx=lin+w, t=idx/3, j=idx-t*3;
                vv[w] = s_in[t*83+j];
            }
            d4[i] = make_float4(vv[0],vv[1],vv[2],vv[3]);
        }
        /* rotations */
        d4 = (float4*)(out + OFF_ROT + (size_t)g0*4);
        for (int i=tid; i<GPB; i+=THR){
            const float* rt = s_in + i*83 + 3;
            d4[i] = make_float4(rt[0],rt[1],rt[2],rt[3]);
        }
    }
}

/* ------------------------------------------------------------------ */
extern "C" void kernel_launch(void* const* d_in, const int* in_sizes, int n_in,
                              void* d_out, int out_size){
    const float* ext    = (const float*)d_in[0];
    const float* intr   = (const float*)d_in[1];
    const float* coords = (const float*)d_in[2];
    const float* depths = (const float*)d_in[3];
    const float* opac   = (const float*)d_in[4];
    const float* raw    = (const float*)d_in[5];
    const float* gf     = (const float*)d_in[6];
    const void*  ph     = (n_in > 7) ? d_in[7] : nullptr;
    const void*  pw     = (n_in > 8) ? d_in[8] : nullptr;
    float* out = (float*)d_out;

    setup_kernel<<<BB*5, 32>>>(ext, intr, ph, pw);

    size_t smem = (size_t)(GPB*83 + NHW*FTS + 165 + 24)*sizeof(float);
    cudaFuncSetAttribute(gauss_kernel, cudaFuncAttributeMaxDynamicSharedMemorySize, (int)smem);
    gauss_kernel<<<NG/GPB, THR, smem>>>(coords, depths, opac, raw, gf, out);
}

// round 12
// speedup vs baseline: 1.0941x; 1.0941x over previous
#include <cuda_runtime.h>
#include <math.h>

#define BB   4
#define HWD  16384
#define SPPX 3
#define CCH  64
#define NG   (BB*HWD*SPPX)      /* 196608 gaussians */
#define GPB  128                /* gaussians per block */
#define THR  128                /* 1 thread per gaussian */
#define NGB  (HWD*SPPX)         /* gaussians per batch = 49152 */
#define NHW  44                 /* hw rows per block tile */
#define FTS  68                 /* feat tile row stride */
#define RST  84                 /* s_in row stride (16B aligned, conflict-free) */

/* output layout (floats): means|cov|sh|opa|feat|scales|rot */
#define OFF_MEANS ((size_t)0)
#define OFF_COV   ((size_t)3*NG)
#define OFF_SH    ((size_t)12*NG)
#define OFF_OPA   ((size_t)87*NG)
#define OFF_FEAT  ((size_t)88*NG)
#define OFF_SCL   ((size_t)152*NG)
#define OFF_ROT   ((size_t)155*NG)

static __device__ const int d_LOFF[5] = {0,1,10,35,84};

__device__ float g_D[BB*165];   /* Wigner D per batch, concat l=0..4 */
__device__ float g_cb[BB*24];   /* per-batch consts: R(9) o(3) Kinv(9) mult */

/* ------------------------------------------------------------------ */
__device__ __forceinline__ void wmmf(const float* A, const float* B, float* C,
                                     int n, int lane){
    for (int idx=lane; idx<n*n; idx+=32){
        int r=idx/n, c=idx-r*n;
        float s=0.f;
        for (int k=0;k<n;k++) s += A[r*n+k]*B[k*n+c];
        C[idx]=s;
    }
}

/* Taylor expm (9 terms, threshold 1.0, scaling & squaring) */
__device__ void wexpmf(float theta, const float* G, int n, int lane,
                       float* M, float* P, float* T){
    const int n2=n*n;
    for (int i=lane;i<n2;i+=32) M[i]=theta*G[i];
    __syncwarp();
    int s=0;
    if (lane==0){
        float nm=0.f;
        for (int r=0;r<n;r++){
            float rs=0.f;
            for (int c=0;c<n;c++) rs += fabsf(M[r*n+c]);
            nm = fmaxf(nm, rs);
        }
        while (nm > 1.0f){ nm*=0.5f; s++; }
    }
    s = __shfl_sync(0xffffffffu, s, 0);
    float scl = ldexpf(1.0f, -s);
    for (int i=lane;i<n2;i+=32) M[i]*=scl;
    __syncwarp();
    for (int i=lane;i<n2;i+=32) P[i] = ((i/n)==(i%n)) ? 1.0f : 0.0f;
    __syncwarp();
    for (int k=9;k>=1;k--){
        wmmf(M,P,T,n,lane); __syncwarp();
        float ik = 1.0f/(float)k;
        for (int i=lane;i<n2;i+=32)
            P[i] = T[i]*ik + (((i/n)==(i%n)) ? 1.0f : 0.0f);
        __syncwarp();
    }
    for (int it=0; it<s; it++){
        wmmf(P,P,T,n,lane); __syncwarp();
        for (int i=lane;i<n2;i+=32) P[i]=T[i];
        __syncwarp();
    }
}

__device__ __forceinline__ int read_dim(const void* p, int defv){
    if (!p) return defv;
    int iv = *(const int*)p;
    if (iv>=1 && iv<=(1<<20)) return iv;
    float fv = *(const float*)p;
    if (fv>=1.0f && fv<=1048576.0f) return (int)(fv+0.5f);
    return defv;
}

/* ------------------------------------------------------------------ */
/* Setup kernel: grid = BB*5 (b,l), block = 32. Closed-form EA/EC,    */
/* short-Taylor EB, D = EA (EB EC).                                   */
__global__ void setup_kernel(const float* __restrict__ ext,
                             const float* __restrict__ intr,
                             const void* ph, const void* pw){
    const int b = blockIdx.x/5, l = blockIdx.x%5;
    const int n = 2*l+1, n2 = n*n;
    const int lane = threadIdx.x;
    __shared__ float Qre[81],Qim[81],Sre[81],Tre[81],Tim[81];
    __shared__ float Gx[81],EA[81],EB[81],EC[81],M[81],P[81],W[81];
    __shared__ float cs[9], sn[9], cg[9], sg2[9];

    for (int i=lane;i<n2;i+=32){ Qre[i]=0.f; Qim[i]=0.f; }
    __syncwarp();
    if (lane==0){
        const float is2 = 0.70710678118654752440f;
        for (int m=-l;m<0;m++){
            Qre[(l+m)*n+(l-m)] = is2;
            Qim[(l+m)*n+(l+m)] = -is2;
        }
        Qre[l*n+l] = 1.0f;
        for (int m=1;m<=l;m++){
            float sgn = (m&1)? -1.0f : 1.0f;
            Qre[(l+m)*n+(l+m)] = sgn*is2;
            Qim[(l+m)*n+(l-m)] = sgn*is2;
        }
    }
    __syncwarp();
    {
        float cr,ci;
        switch (l&3){
            case 0: cr=1;  ci=0;  break;
            case 1: cr=0;  ci=-1; break;
            case 2: cr=-1; ci=0;  break;
            default:cr=0;  ci=1;  break;
        }
        for (int i=lane;i<n2;i+=32){
            float re=Qre[i], im=Qim[i];
            Qre[i]=re*cr-im*ci; Qim[i]=re*ci+im*cr;
        }
    }
    __syncwarp();

    for (int i=lane;i<n2;i+=32) Sre[i]=0.f;
    __syncwarp();
    if (lane==0){
        float jj=(float)l;
        for (int i=0;i<n-1;i++){
            float m = -jj + (float)i;
            float sq = sqrtf(jj*(jj+1.0f) - m*(m+1.0f));
            Sre[(i+1)*n+i] = -0.5f*sq; Sre[i*n+(i+1)] = 0.5f*sq;
        }
    }
    __syncwarp();
    for (int idx=lane; idx<n2; idx+=32){
        int r=idx/n, c=idx-r*n;
        float sre=0.f, sim=0.f;
        for (int k=0;k<n;k++){
            float xr=Sre[r*n+k];
            sre += xr*Qre[k*n+c]; sim += xr*Qim[k*n+c];
        }
        Tre[idx]=sre; Tim[idx]=sim;
    }
    __syncwarp();
    for (int idx=lane; idx<n2; idx+=32){
        int r=idx/n, c=idx-r*n;
        float s=0.f;
        for (int k=0;k<n;k++)
            s += Qre[k*n+r]*Tre[k*n+c] + Qim[k*n+r]*Tim[k*n+c];
        Gx[idx] = s;
    }
    __syncwarp();

    float al=0.f, be=0.f, ga=0.f;
    if (lane==0){
        float R[3][3];
        for (int r=0;r<3;r++) for (int c=0;c<3;c++) R[r][c] = ext[b*16+r*4+c];
        float x0=R[0][1], x1=R[1][1], x2=R[2][1];
        float inv = 1.0f/sqrtf(x0*x0+x1*x1+x2*x2);
        x0*=inv; x1*=inv; x2*=inv;
        be = acosf(fminf(1.0f, fmaxf(-1.0f, x1)));
        al = atan2f(x0, x2);
        float ca=cosf(al), sa=sinf(al);
        float Rp00 = ca*R[0][0] - sa*R[2][0];
        float Rp02 = ca*R[0][2] - sa*R[2][2];
        ga = atan2f(Rp02, Rp00);
    }
    al = __shfl_sync(0xffffffffu, al, 0);
    be = __shfl_sync(0xffffffffu, be, 0);
    ga = __shfl_sync(0xffffffffu, ga, 0);

    if (lane < n){
        float m = (float)(lane - l);
        cs[lane] = cosf(m*al);  sn[lane]  = sinf(m*al);
        cg[lane] = cosf(m*ga);  sg2[lane] = sinf(m*ga);
    }
    __syncwarp();
    for (int idx=lane; idx<n2; idx+=32){
        int r=idx/n, c=idx-r*n;
        float sa_=0.f, sc_=0.f;
        for (int k=0;k<n;k++){
            float ar=Qre[k*n+r], ai=Qim[k*n+r];
            float br=Qre[k*n+c], bi=Qim[k*n+c];
            float pre = ar*br + ai*bi;
            float pim = ar*bi - ai*br;
            sa_ += pre*cs[k] - pim*sn[k];
            sc_ += pre*cg[k] - pim*sg2[k];
        }
        EA[idx]=sa_; EC[idx]=sc_;
    }
    __syncwarp();

    wexpmf(-be, Gx, n, lane, M,P,W);
    for (int i=lane;i<n2;i+=32) EB[i]=P[i];
    __syncwarp();

    wmmf(EB,EC,W,n,lane); __syncwarp();
    wmmf(EA,W,M,n,lane);  __syncwarp();
    for (int i=lane;i<n2;i+=32)
        g_D[b*165 + d_LOFF[l] + i] = M[i];

    if (l==0 && lane==0){
        float K[3][3];
        for (int r=0;r<3;r++) for (int c=0;c<3;c++) K[r][c]=intr[b*9+r*3+c];
        float det = K[0][0]*(K[1][1]*K[2][2]-K[1][2]*K[2][1])
                  - K[0][1]*(K[1][0]*K[2][2]-K[1][2]*K[2][0])
                  + K[0][2]*(K[1][0]*K[2][1]-K[1][1]*K[2][0]);
        float id = 1.0f/det;
        float Ki[3][3];
        Ki[0][0]=(K[1][1]*K[2][2]-K[1][2]*K[2][1])*id;
        Ki[0][1]=(K[0][2]*K[2][1]-K[0][1]*K[2][2])*id;
        Ki[0][2]=(K[0][1]*K[1][2]-K[0][2]*K[1][1])*id;
        Ki[1][0]=(K[1][2]*K[2][0]-K[1][0]*K[2][2])*id;
        Ki[1][1]=(K[0][0]*K[2][2]-K[0][2]*K[2][0])*id;
        Ki[1][2]=(K[0][2]*K[1][0]-K[0][0]*K[1][2])*id;
        Ki[2][0]=(K[1][0]*K[2][1]-K[1][1]*K[2][0])*id;
        Ki[2][1]=(K[0][1]*K[2][0]-K[0][0]*K[2][1])*id;
        Ki[2][2]=(K[0][0]*K[1][1]-K[0][1]*K[1][0])*id;

        int Hh = read_dim(ph, 128);
        int Ww = read_dim(pw, 128);
        float psx = 1.0f/(float)Ww, psy = 1.0f/(float)Hh;
        float d2  = K[0][0]*K[1][1]-K[0][1]*K[1][0];
        float v0  = ( K[1][1]*psx - K[0][1]*psy)/d2;
        float v1  = (-K[1][0]*psx + K[0][0]*psy)/d2;
        float mult = 0.1f*(v0+v1);

        float* cb = g_cb + b*24;
        for (int r=0;r<3;r++) for (int c=0;c<3;c++) cb[r*3+c]=ext[b*16+r*4+c];
        for (int r=0;r<3;r++) cb[9+r]=ext[b*16+r*4+3];
        for (int r=0;r<3;r++) for (int c=0;c<3;c++) cb[12+r*3+c]=Ki[r][c];
        cb[21]=mult;
    }
}

/* ------------------------------------------------------------------ */
/* Main kernel: 1 thread per gaussian; row stride 84 with +1 shift so */
/* quat (4-7) and SH (8-82) are 16B aligned; SH rotated in registers. */
__global__ void __launch_bounds__(THR, 4)
gauss_kernel(const float* __restrict__ coords, const float* __restrict__ depths,
             const float* __restrict__ opac,   const float* __restrict__ raw,
             const float* __restrict__ gf,     float* __restrict__ out){
    extern __shared__ float sm[];
    float* s_in = sm;                  /* GPB*RST */
    float* s_ft = s_in + GPB*RST;      /* NHW*FTS feat tile [hw][c] */
    float* s_D  = s_ft + NHW*FTS;      /* 165 (mask folded in)      */
    float* s_cb = s_D  + 165;          /* 24                        */

    const int tid  = threadIdx.x;
    const int g0   = blockIdx.x*GPB;
    const int b    = g0/NGB;
    const int idx0 = g0 - b*NGB;
    const int hw0  = idx0/3;

    {
        const float MSK[5] = {1.0f, 0.025f, 0.00625f, 0.0015625f, 0.000390625f};
        for (int i=tid;i<165;i+=THR){
            int l = (i>=84)?4:(i>=35)?3:(i>=10)?2:(i>=1)?1:0;
            s_D[i] = g_D[b*165+i]*MSK[l];
        }
    }
    if (tid < 24) s_cb[tid] = g_cb[b*24+tid];

    /* stage feat tile: [hw][c], coalesced gmem reads */
    {
        const float* gfb = gf + (size_t)b*CCH*HWD;
        #pragma unroll 4
        for (int i=tid; i<CCH*NHW; i+=THR){
            int c = i/NHW, j = i - c*NHW;
            int hwrow = hw0 + j;
            float v = (hwrow < HWD) ? gfb[(size_t)c*HWD + hwrow] : 0.f;
            s_ft[j*FTS + c] = v;
        }
    }

    /* stage raw_gaussians: coalesced float4 loads -> rows at +1 shift */
    {
        const float4* src = reinterpret_cast<const float4*>(raw + (size_t)g0*82);
        #pragma unroll 4
        for (int i=tid; i<GPB*82/4; i+=THR){
            float4 v = src[i];
            int lin = i*4;
            float vv[4] = {v.x, v.y, v.z, v.w};
            #pragma unroll
            for (int w=0; w<4; w++){
                int t = (lin+w)/82;
                int j = (lin+w) - t*82;
                s_in[t*RST + j + 1] = vv[w];
            }
        }
    }
    __syncthreads();

    const int g = g0 + tid;
    float* in = s_in + tid*RST;        /* slot k holds raw[k-1] */
    const float depth = depths[g];
    const float2 uv = reinterpret_cast<const float2*>(coords)[g];
    out[OFF_OPA + g] = opac[g];

    /* scales (raw[0..2] at slots 1..3) */
    const float mult = s_cb[21];
    float sc[3];
    #pragma unroll
    for (int i=0;i<3;i++){
        float x = in[1+i];
        float sig = __fdividef(1.0f, 1.0f + __expf(-x));
        sc[i] = (0.5f + 14.5f*sig) * depth * mult;
    }
    /* quaternion (raw[3..6] at slots 4..7, aligned) */
    float q0,q1,q2,q3;
    {
        float4 q = *reinterpret_cast<const float4*>(in + 4);
        q0=q.x; q1=q.y; q2=q.z; q3=q.w;
    }
    float nq = sqrtf(q0*q0+q1*q1+q2*q2+q3*q3);
    float invq = __fdividef(1.0f, nq + 1e-8f);
    q0*=invq; q1*=invq; q2*=invq; q3*=invq;
    float ss = __fdividef(2.0f, q0*q0+q1*q1+q2*q2+q3*q3);
    const float r=q0, ii=q1, jj=q2, kk=q3;
    float R00=1.f-ss*(jj*jj+kk*kk), R01=ss*(ii*jj-kk*r), R02=ss*(ii*kk+jj*r);
    float R10=ss*(ii*jj+kk*r), R11=1.f-ss*(ii*ii+kk*kk), R12=ss*(jj*kk-ii*r);
    float R20=ss*(ii*kk-jj*r), R21=ss*(jj*kk+ii*r), R22=1.f-ss*(ii*ii+jj*jj);
    float v0=sc[0]*sc[0], v1=sc[1]*sc[1], v2=sc[2]*sc[2];

    /* means: direct gmem write */
    {
        float dx = s_cb[12]*uv.x + s_cb[13]*uv.y + s_cb[14];
        float dy = s_cb[15]*uv.x + s_cb[16]*uv.y + s_cb[17];
        float dz = s_cb[18]*uv.x + s_cb[19]*uv.y + s_cb[20];
        float dn = rsqrtf(dx*dx+dy*dy+dz*dz);
        dx*=dn; dy*=dn; dz*=dn;
        float wx = s_cb[0]*dx + s_cb[1]*dy + s_cb[2]*dz;
        float wy = s_cb[3]*dx + s_cb[4]*dy + s_cb[5]*dz;
        float wz = s_cb[6]*dx + s_cb[7]*dy + s_cb[8]*dz;
        float* mo = out + OFF_MEANS + (size_t)g*3;
        mo[0] = s_cb[9]  + wx*depth;
        mo[1] = s_cb[10] + wy*depth;
        mo[2] = s_cb[11] + wz*depth;
    }
    /* covariance: direct gmem write */
    {
        float c00=R00*R00*v0+R01*R01*v1+R02*R02*v2;
        float c01=R00*R10*v0+R01*R11*v1+R02*R12*v2;
        float c02=R00*R20*v0+R01*R21*v1+R02*R22*v2;
        float c11=R10*R10*v0+R11*R11*v1+R12*R12*v2;
        float c12=R10*R20*v0+R11*R21*v1+R12*R22*v2;
        float c22=R20*R20*v0+R21*R21*v1+R22*R22*v2;
        float* co = out + OFF_COV + (size_t)g*9;
        co[0]=c00; co[1]=c01; co[2]=c02;
        co[3]=c01; co[4]=c11; co[5]=c12;
        co[6]=c02; co[7]=c12; co[8]=c22;
    }

    /* SH rotation fully in registers: load 75 via 18 LDS128 + 3 LDS */
    {
        float v[75];
        #pragma unroll
        for (int q=0;q<18;q++){
            float4 x = *reinterpret_cast<const float4*>(in + 8 + 4*q);
            v[4*q]=x.x; v[4*q+1]=x.y; v[4*q+2]=x.z; v[4*q+3]=x.w;
        }
        v[72]=in[80]; v[73]=in[81]; v[74]=in[82];

        const float d0 = s_D[0];
        v[0]*=d0; v[25]*=d0; v[50]*=d0;
        const int LOFFc[5] = {0,1,10,35,84};
        #pragma unroll
        for (int l=1;l<5;l++){
            const int n = 2*l+1, off = l*l;
            const float* D = s_D + LOFFc[l];
            float a0[9], a1[9], a2[9];
            #pragma unroll
            for (int i=0;i<n;i++){
                float s0=0.f, s1=0.f, s2=0.f;
                #pragma unroll
                for (int j=0;j<n;j++){
                    float d = D[i*n+j];
                    s0 += d*v[off+j]; s1 += d*v[25+off+j]; s2 += d*v[50+off+j];
                }
                a0[i]=s0; a1[i]=s1; a2[i]=s2;
            }
            #pragma unroll
            for (int i=0;i<n;i++){
                v[off+i]=a0[i]; v[25+off+i]=a1[i]; v[50+off+i]=a2[i];
            }
        }

        #pragma unroll
        for (int q=0;q<18;q++){
            *reinterpret_cast<float4*>(in + 8 + 4*q) =
                make_float4(v[4*q], v[4*q+1], v[4*q+2], v[4*q+3]);
        }
        in[80]=v[72]; in[81]=v[73]; in[82]=v[74];
    }
    /* stash scales (slots 1-3) + normalized quat (slots 4-7) */
    in[1]=sc[0]; in[2]=sc[1]; in[3]=sc[2];
    *reinterpret_cast<float4*>(in + 4) = make_float4(q0,q1,q2,q3);
    __syncthreads();

    /* coalesced float4 flush */
    {
        /* SH: gather from slot 8.. */
        float4* d4 = (float4*)(out + OFF_SH + (size_t)g0*75);
        #pragma unroll 4
        for (int i=tid; i<GPB*75/4; i+=THR){
            int lin = i*4; float vv[4];
            #pragma unroll
            for (int w=0;w<4;w++){
                int idx=lin+w, t=idx/75, j=idx-t*75;
                vv[w] = s_in[t*RST+8+j];
            }
            d4[i] = make_float4(vv[0],vv[1],vv[2],vv[3]);
        }
        /* features: LDS128 from [hw][c] tile */
        d4 = (float4*)(out + OFF_FEAT + (size_t)g0*64);
        #pragma unroll 4
        for (int i=tid; i<GPB*64/4; i+=THR){
            int lin = i*4;
            int gg  = lin>>6;
            int c0  = lin & 63;
            int hwl = (idx0+gg)/3 - hw0;
            d4[i] = *reinterpret_cast<const float4*>(&s_ft[hwl*FTS + c0]);
        }
        /* scales: gather from slots 1-3 */
        d4 = (float4*)(out + OFF_SCL + (size_t)g0*3);
        for (int i=tid; i<GPB*3/4; i+=THR){
            int lin=i*4; float vv[4];
            #pragma unroll
            for (int w=0;w<4;w++){
                int idx=lin+w, t=idx/3, j=idx-t*3;
                vv[w] = s_in[t*RST+1+j];
            }
            d4[i] = make_float4(vv[0],vv[1],vv[2],vv[3]);
        }
        /* rotations: aligned LDS128 from slot 4 */
        d4 = (float4*)(out + OFF_ROT + (size_t)g0*4);
        for (int i=tid; i<GPB; i+=THR){
            d4[i] = *reinterpret_cast<const float4*>(s_in + i*RST + 4);
        }
    }
}

/* ------------------------------------------------------------------ */
extern "C" void kernel_launch(void* const* d_in, const int* in_sizes, int n_in,
                              void* d_out, int out_size){
    const float* ext    = (const float*)d_in[0];
    const float* intr   = (const float*)d_in[1];
    const float* coords = (const float*)d_in[2];
    const float* depths = (const float*)d_in[3];
    const float* opac   = (const float*)d_in[4];
    const float* raw    = (const float*)d_in[5];
    const float* gf     = (const float*)d_in[6];
    const void*  ph     = (n_in > 7) ? d_in[7] : nullptr;
    const void*  pw     = (n_in > 8) ? d_in[8] : nullptr;
    float* out = (float*)d_out;

    setup_kernel<<<BB*5, 32>>>(ext, intr, ph, pw);

    size_t smem = (size_t)(GPB*RST + NHW*FTS + 165 + 24)*sizeof(float);
    cudaFuncSetAttribute(gauss_kernel, cudaFuncAttributeMaxDynamicSharedMemorySize, (int)smem);
    gauss_kernel<<<NG/GPB, THR, smem>>>(coords, depths, opac, raw, gf, out);
}

// round 14
// speedup vs baseline: 1.2342x; 1.1281x over previous
#include <cuda_runtime.h>
#include <math.h>

#define BB   4
#define HWD  16384
#define SPPX 3
#define CCH  64
#define NG   (BB*HWD*SPPX)      /* 196608 gaussians */
#define GPB  128                /* gaussians per block */
#define THR  128                /* 1 thread per gaussian */
#define NGB  (HWD*SPPX)         /* gaussians per batch = 49152 */
#define NHW  44                 /* hw rows per block tile */
#define FTS  68                 /* feat tile row stride */
#define RST  84                 /* s_in row stride (16B aligned, conflict-free) */

/* output layout (floats): means|cov|sh|opa|feat|scales|rot */
#define OFF_MEANS ((size_t)0)
#define OFF_COV   ((size_t)3*NG)
#define OFF_SH    ((size_t)12*NG)
#define OFF_OPA   ((size_t)87*NG)
#define OFF_FEAT  ((size_t)88*NG)
#define OFF_SCL   ((size_t)152*NG)
#define OFF_ROT   ((size_t)155*NG)

static __device__ const int d_LOFF[5] = {0,1,10,35,84};

__device__ float g_D[BB*165];   /* Wigner D per batch, concat l=0..4 */
__device__ float g_cb[BB*24];   /* per-batch consts: R(9) o(3) Kinv(9) mult */

/* ------------------------------------------------------------------ */
__device__ __forceinline__ void wmmf(const float* A, const float* B, float* C,
                                     int n, int lane){
    for (int idx=lane; idx<n*n; idx+=32){
        int r=idx/n, c=idx-r*n;
        float s=0.f;
        for (int k=0;k<n;k++) s += A[r*n+k]*B[k*n+c];
        C[idx]=s;
    }
}

/* Register-resident expm: lane j owns column j of P; M fully in regs.  */
/* 9-term Horner Taylor (no smem/sync in loop) + shfl-based squarings.  */
template<int L>
__device__ __forceinline__ void eb_reg(float be, const float* __restrict__ Gx,
                                       float* __restrict__ EBout){
    constexpr int N = 2*L+1;
    const int lane = threadIdx.x & 31;

    float m[N][N];
    float nrm = 0.f;
    #pragma unroll
    for (int i=0;i<N;i++){
        float rs=0.f;
        #pragma unroll
        for (int k=0;k<N;k++){
            float v = -be*Gx[i*N+k];
            m[i][k] = v;
            rs += fabsf(v);
        }
        nrm = fmaxf(nrm, rs);
    }
    int s=0;
    while (nrm > 1.0f){ nrm*=0.5f; s++; }
    float scl = ldexpf(1.0f, -s);
    #pragma unroll
    for (int i=0;i<N;i++)
        #pragma unroll
        for (int k=0;k<N;k++) m[i][k]*=scl;

    const int j = lane;                 /* column owner (garbage for j>=N) */
    float col[N];
    #pragma unroll
    for (int i=0;i<N;i++) col[i] = (i==j)?1.f:0.f;

    #pragma unroll
    for (int k=9;k>=1;k--){
        float nc[N];
        const float ik = 1.0f/(float)k;
        #pragma unroll
        for (int i=0;i<N;i++){
            float acc=0.f;
            #pragma unroll
            for (int t=0;t<N;t++) acc += m[i][t]*col[t];
            nc[i] = acc*ik + ((i==j)?1.f:0.f);
        }
        #pragma unroll
        for (int i=0;i<N;i++) col[i]=nc[i];
    }

    for (int it=0; it<s; it++){
        float nc[N];
        #pragma unroll
        for (int i=0;i<N;i++) nc[i]=0.f;
        #pragma unroll
        for (int k=0;k<N;k++){
            const float ck = col[k];    /* P[k][j] local */
            #pragma unroll
            for (int i=0;i<N;i++){
                float pik = __shfl_sync(0xffffffffu, col[i], k); /* P[i][k] */
                nc[i] += pik*ck;
            }
        }
        #pragma unroll
        for (int i=0;i<N;i++) col[i]=nc[i];
        __syncwarp();
    }

    if (lane < N){
        #pragma unroll
        for (int i=0;i<N;i++) EBout[i*N+lane]=col[i];
    }
    __syncwarp();
}

__device__ __forceinline__ int read_dim(const void* p, int defv){
    if (!p) return defv;
    int iv = *(const int*)p;
    if (iv>=1 && iv<=(1<<20)) return iv;
    float fv = *(const float*)p;
    if (fv>=1.0f && fv<=1048576.0f) return (int)(fv+0.5f);
    return defv;
}

/* ------------------------------------------------------------------ */
/* Setup kernel: grid = BB*5 (b,l), block = 32. Closed-form EA/EC,    */
/* register-expm EB, D = EA (EB EC).                                  */
__global__ void setup_kernel(const float* __restrict__ ext,
                             const float* __restrict__ intr,
                             const void* ph, const void* pw){
    const int b = blockIdx.x/5, l = blockIdx.x%5;
    const int n = 2*l+1, n2 = n*n;
    const int lane = threadIdx.x;
    __shared__ float Qre[81],Qim[81],Sre[81],Tre[81],Tim[81];
    __shared__ float Gx[81],EA[81],EB[81],EC[81],M[81],W[81];
    __shared__ float cs[9], sn[9], cg[9], sg2[9];

    for (int i=lane;i<n2;i+=32){ Qre[i]=0.f; Qim[i]=0.f; }
    __syncwarp();
    if (lane==0){
        const float is2 = 0.70710678118654752440f;
        for (int m=-l;m<0;m++){
            Qre[(l+m)*n+(l-m)] = is2;
            Qim[(l+m)*n+(l+m)] = -is2;
        }
        Qre[l*n+l] = 1.0f;
        for (int m=1;m<=l;m++){
            float sgn = (m&1)? -1.0f : 1.0f;
            Qre[(l+m)*n+(l+m)] = sgn*is2;
            Qim[(l+m)*n+(l-m)] = sgn*is2;
        }
    }
    __syncwarp();
    {
        float cr,ci;
        switch (l&3){
            case 0: cr=1;  ci=0;  break;
            case 1: cr=0;  ci=-1; break;
            case 2: cr=-1; ci=0;  break;
            default:cr=0;  ci=1;  break;
        }
        for (int i=lane;i<n2;i+=32){
            float re=Qre[i], im=Qim[i];
            Qre[i]=re*cr-im*ci; Qim[i]=re*ci+im*cr;
        }
    }
    __syncwarp();

    /* Gx = Re(Q^H X0 Q), X0 real antisymmetric */
    for (int i=lane;i<n2;i+=32) Sre[i]=0.f;
    __syncwarp();
    if (lane==0){
        float jj=(float)l;
        for (int i=0;i<n-1;i++){
            float m = -jj + (float)i;
            float sq = sqrtf(jj*(jj+1.0f) - m*(m+1.0f));
            Sre[(i+1)*n+i] = -0.5f*sq; Sre[i*n+(i+1)] = 0.5f*sq;
        }
    }
    __syncwarp();
    for (int idx=lane; idx<n2; idx+=32){
        int r=idx/n, c=idx-r*n;
        float sre=0.f, sim=0.f;
        for (int k=0;k<n;k++){
            float xr=Sre[r*n+k];
            sre += xr*Qre[k*n+c]; sim += xr*Qim[k*n+c];
        }
        Tre[idx]=sre; Tim[idx]=sim;
    }
    __syncwarp();
    for (int idx=lane; idx<n2; idx+=32){
        int r=idx/n, c=idx-r*n;
        float s=0.f;
        for (int k=0;k<n;k++)
            s += Qre[k*n+r]*Tre[k*n+c] + Qim[k*n+r]*Tim[k*n+c];
        Gx[idx] = s;
    }
    __syncwarp();

    /* angles */
    float al=0.f, be=0.f, ga=0.f;
    if (lane==0){
        float R[3][3];
        for (int r=0;r<3;r++) for (int c=0;c<3;c++) R[r][c] = ext[b*16+r*4+c];
        float x0=R[0][1], x1=R[1][1], x2=R[2][1];
        float inv = 1.0f/sqrtf(x0*x0+x1*x1+x2*x2);
        x0*=inv; x1*=inv; x2*=inv;
        be = acosf(fminf(1.0f, fmaxf(-1.0f, x1)));
        al = atan2f(x0, x2);
        float ca=cosf(al), sa=sinf(al);
        float Rp00 = ca*R[0][0] - sa*R[2][0];
        float Rp02 = ca*R[0][2] - sa*R[2][2];
        ga = atan2f(Rp02, Rp00);
    }
    al = __shfl_sync(0xffffffffu, al, 0);
    be = __shfl_sync(0xffffffffu, be, 0);
    ga = __shfl_sync(0xffffffffu, ga, 0);

    /* EA, EC closed form: e^{a X1} = Q^H diag(e^{i m a}) Q */
    if (lane < n){
        float m = (float)(lane - l);
        cs[lane] = cosf(m*al);  sn[lane]  = sinf(m*al);
        cg[lane] = cosf(m*ga);  sg2[lane] = sinf(m*ga);
    }
    __syncwarp();
    for (int idx=lane; idx<n2; idx+=32){
        int r=idx/n, c=idx-r*n;
        float sa_=0.f, sc_=0.f;
        for (int k=0;k<n;k++){
            float ar=Qre[k*n+r], ai=Qim[k*n+r];
            float br=Qre[k*n+c], bi=Qim[k*n+c];
            float pre = ar*br + ai*bi;
            float pim = ar*bi - ai*br;
            sa_ += pre*cs[k] - pim*sn[k];
            sc_ += pre*cg[k] - pim*sg2[k];
        }
        EA[idx]=sa_; EC[idx]=sc_;
    }
    __syncwarp();

    /* EB = e^{-beta Gx}: register expm, templated on l */
    switch (l){
        case 0: eb_reg<0>(be, Gx, EB); break;
        case 1: eb_reg<1>(be, Gx, EB); break;
        case 2: eb_reg<2>(be, Gx, EB); break;
        case 3: eb_reg<3>(be, Gx, EB); break;
        default: eb_reg<4>(be, Gx, EB); break;
    }

    wmmf(EB,EC,W,n,lane); __syncwarp();
    wmmf(EA,W,M,n,lane);  __syncwarp();
    for (int i=lane;i<n2;i+=32)
        g_D[b*165 + d_LOFF[l] + i] = M[i];

    if (l==0 && lane==0){
        float K[3][3];
        for (int r=0;r<3;r++) for (int c=0;c<3;c++) K[r][c]=intr[b*9+r*3+c];
        float det = K[0][0]*(K[1][1]*K[2][2]-K[1][2]*K[2][1])
                  - K[0][1]*(K[1][0]*K[2][2]-K[1][2]*K[2][0])
                  + K[0][2]*(K[1][0]*K[2][1]-K[1][1]*K[2][0]);
        float id = 1.0f/det;
        float Ki[3][3];
        Ki[0][0]=(K[1][1]*K[2][2]-K[1][2]*K[2][1])*id;
        Ki[0][1]=(K[0][2]*K[2][1]-K[0][1]*K[2][2])*id;
        Ki[0][2]=(K[0][1]*K[1][2]-K[0][2]*K[1][1])*id;
        Ki[1][0]=(K[1][2]*K[2][0]-K[1][0]*K[2][2])*id;
        Ki[1][1]=(K[0][0]*K[2][2]-K[0][2]*K[2][0])*id;
        Ki[1][2]=(K[0][2]*K[1][0]-K[0][0]*K[1][2])*id;
        Ki[2][0]=(K[1][0]*K[2][1]-K[1][1]*K[2][0])*id;
        Ki[2][1]=(K[0][1]*K[2][0]-K[0][0]*K[2][1])*id;
        Ki[2][2]=(K[0][0]*K[1][1]-K[0][1]*K[1][0])*id;

        int Hh = read_dim(ph, 128);
        int Ww = read_dim(pw, 128);
        float psx = 1.0f/(float)Ww, psy = 1.0f/(float)Hh;
        float d2  = K[0][0]*K[1][1]-K[0][1]*K[1][0];
        float v0  = ( K[1][1]*psx - K[0][1]*psy)/d2;
        float v1  = (-K[1][0]*psx + K[0][0]*psy)/d2;
        float mult = 0.1f*(v0+v1);

        float* cb = g_cb + b*24;
        for (int r=0;r<3;r++) for (int c=0;c<3;c++) cb[r*3+c]=ext[b*16+r*4+c];
        for (int r=0;r<3;r++) cb[9+r]=ext[b*16+r*4+3];
        for (int r=0;r<3;r++) for (int c=0;c<3;c++) cb[12+r*3+c]=Ki[r][c];
        cb[21]=mult;
    }
}

/* ------------------------------------------------------------------ */
/* Main kernel: 1 thread per gaussian; row stride 84 with +1 shift so */
/* quat (4-7) and SH (8-82) are 16B aligned; SH rotated in registers. */
__global__ void __launch_bounds__(THR, 4)
gauss_kernel(const float* __restrict__ coords, const float* __restrict__ depths,
             const float* __restrict__ opac,   const float* __restrict__ raw,
             const float* __restrict__ gf,     float* __restrict__ out){
    extern __shared__ float sm[];
    float* s_in = sm;                  /* GPB*RST */
    float* s_ft = s_in + GPB*RST;      /* NHW*FTS feat tile [hw][c] */
    float* s_D  = s_ft + NHW*FTS;      /* 165 (mask folded in)      */
    float* s_cb = s_D  + 165;          /* 24                        */

    const int tid  = threadIdx.x;
    const int g0   = blockIdx.x*GPB;
    const int b    = g0/NGB;
    const int idx0 = g0 - b*NGB;
    const int hw0  = idx0/3;

    {
        const float MSK[5] = {1.0f, 0.025f, 0.00625f, 0.0015625f, 0.000390625f};
        for (int i=tid;i<165;i+=THR){
            int l = (i>=84)?4:(i>=35)?3:(i>=10)?2:(i>=1)?1:0;
            s_D[i] = g_D[b*165+i]*MSK[l];
        }
    }
    if (tid < 24) s_cb[tid] = g_cb[b*24+tid];

    /* stage feat tile: [hw][c], coalesced gmem reads */
    {
        const float* gfb = gf + (size_t)b*CCH*HWD;
        #pragma unroll 4
        for (int i=tid; i<CCH*NHW; i+=THR){
            int c = i/NHW, j = i - c*NHW;
            int hwrow = hw0 + j;
            float v = (hwrow < HWD) ? gfb[(size_t)c*HWD + hwrow] : 0.f;
            s_ft[j*FTS + c] = v;
        }
    }

    /* stage raw_gaussians: coalesced float4 loads -> rows at +1 shift */
    {
        const float4* src = reinterpret_cast<const float4*>(raw + (size_t)g0*82);
        #pragma unroll 4
        for (int i=tid; i<GPB*82/4; i+=THR){
            float4 v = src[i];
            int lin = i*4;
            float vv[4] = {v.x, v.y, v.z, v.w};
            #pragma unroll
            for (int w=0; w<4; w++){
                int t = (lin+w)/82;
                int j = (lin+w) - t*82;
                s_in[t*RST + j + 1] = vv[w];
            }
        }
    }
    __syncthreads();

    const int g = g0 + tid;
    float* in = s_in + tid*RST;        /* slot k holds raw[k-1] */
    const float depth = depths[g];
    const float2 uv = reinterpret_cast<const float2*>(coords)[g];
    out[OFF_OPA + g] = opac[g];

    /* scales (raw[0..2] at slots 1..3) */
    const float mult = s_cb[21];
    float sc[3];
    #pragma unroll
    for (int i=0;i<3;i++){
        float x = in[1+i];
        float sig = __fdividef(1.0f, 1.0f + __expf(-x));
        sc[i] = (0.5f + 14.5f*sig) * depth * mult;
    }
    /* quaternion (raw[3..6] at slots 4..7, aligned) */
    float q0,q1,q2,q3;
    {
        float4 q = *reinterpret_cast<const float4*>(in + 4);
        q0=q.x; q1=q.y; q2=q.z; q3=q.w;
    }
    float nq = sqrtf(q0*q0+q1*q1+q2*q2+q3*q3);
    float invq = __fdividef(1.0f, nq + 1e-8f);
    q0*=invq; q1*=invq; q2*=invq; q3*=invq;
    float ss = __fdividef(2.0f, q0*q0+q1*q1+q2*q2+q3*q3);
    const float r=q0, ii=q1, jj=q2, kk=q3;
    float R00=1.f-ss*(jj*jj+kk*kk), R01=ss*(ii*jj-kk*r), R02=ss*(ii*kk+jj*r);
    float R10=ss*(ii*jj+kk*r), R11=1.f-ss*(ii*ii+kk*kk), R12=ss*(jj*kk-ii*r);
    float R20=ss*(ii*kk-jj*r), R21=ss*(jj*kk+ii*r), R22=1.f-ss*(ii*ii+jj*jj);
    float v0=sc[0]*sc[0], v1=sc[1]*sc[1], v2=sc[2]*sc[2];

    /* means: direct gmem write */
    {
        float dx = s_cb[12]*uv.x + s_cb[13]*uv.y + s_cb[14];
        float dy = s_cb[15]*uv.x + s_cb[16]*uv.y + s_cb[17];
        float dz = s_cb[18]*uv.x + s_cb[19]*uv.y + s_cb[20];
        float dn = rsqrtf(dx*dx+dy*dy+dz*dz);
        dx*=dn; dy*=dn; dz*=dn;
        float wx = s_cb[0]*dx + s_cb[1]*dy + s_cb[2]*dz;
        float wy = s_cb[3]*dx + s_cb[4]*dy + s_cb[5]*dz;
        float wz = s_cb[6]*dx + s_cb[7]*dy + s_cb[8]*dz;
        float* mo = out + OFF_MEANS + (size_t)g*3;
        mo[0] = s_cb[9]  + wx*depth;
        mo[1] = s_cb[10] + wy*depth;
        mo[2] = s_cb[11] + wz*depth;
    }
    /* covariance: direct gmem write */
    {
        float c00=R00*R00*v0+R01*R01*v1+R02*R02*v2;
        float c01=R00*R10*v0+R01*R11*v1+R02*R12*v2;
        float c02=R00*R20*v0+R01*R21*v1+R02*R22*v2;
        float c11=R10*R10*v0+R11*R11*v1+R12*R12*v2;
        float c12=R10*R20*v0+R11*R21*v1+R12*R22*v2;
        float c22=R20*R20*v0+R21*R21*v1+R22*R22*v2;
        float* co = out + OFF_COV + (size_t)g*9;
        co[0]=c00; co[1]=c01; co[2]=c02;
        co[3]=c01; co[4]=c11; co[5]=c12;
        co[6]=c02; co[7]=c12; co[8]=c22;
    }

    /* SH rotation fully in registers: load 75 via 18 LDS128 + 3 LDS */
    {
        float v[75];
        #pragma unroll
        for (int q=0;q<18;q++){
            float4 x = *reinterpret_cast<const float4*>(in + 8 + 4*q);
            v[4*q]=x.x; v[4*q+1]=x.y; v[4*q+2]=x.z; v[4*q+3]=x.w;
        }
        v[72]=in[80]; v[73]=in[81]; v[74]=in[82];

        const float d0 = s_D[0];
        v[0]*=d0; v[25]*=d0; v[50]*=d0;
        const int LOFFc[5] = {0,1,10,35,84};
        #pragma unroll
        for (int l=1;l<5;l++){
            const int n = 2*l+1, off = l*l;
            const float* D = s_D + LOFFc[l];
            float a0[9], a1[9], a2[9];
            #pragma unroll
            for (int i=0;i<n;i++){
                float s0=0.f, s1=0.f, s2=0.f;
                #pragma unroll
                for (int j=0;j<n;j++){
                    float d = D[i*n+j];
                    s0 += d*v[off+j]; s1 += d*v[25+off+j]; s2 += d*v[50+off+j];
                }
                a0[i]=s0; a1[i]=s1; a2[i]=s2;
            }
            #pragma unroll
            for (int i=0;i<n;i++){
                v[off+i]=a0[i]; v[25+off+i]=a1[i]; v[50+off+i]=a2[i];
            }
        }

        #pragma unroll
        for (int q=0;q<18;q++){
            *reinterpret_cast<float4*>(in + 8 + 4*q) =
                make_float4(v[4*q], v[4*q+1], v[4*q+2], v[4*q+3]);
        }
        in[80]=v[72]; in[81]=v[73]; in[82]=v[74];
    }
    /* stash scales (slots 1-3) + normalized quat (slots 4-7) */
    in[1]=sc[0]; in[2]=sc[1]; in[3]=sc[2];
    *reinterpret_cast<float4*>(in + 4) = make_float4(q0,q1,q2,q3);
    __syncthreads();

    /* coalesced float4 flush */
    {
        /* SH: gather from slot 8.. */
        float4* d4 = (float4*)(out + OFF_SH + (size_t)g0*75);
        #pragma unroll 4
        for (int i=tid; i<GPB*75/4; i+=THR){
            int lin = i*4; float vv[4];
            #pragma unroll
            for (int w=0;w<4;w++){
                int idx=lin+w, t=idx/75, j=idx-t*75;
                vv[w] = s_in[t*RST+8+j];
            }
            d4[i] = make_float4(vv[0],vv[1],vv[2],vv[3]);
        }
        /* features: LDS128 from [hw][c] tile */
        d4 = (float4*)(out + OFF_FEAT + (size_t)g0*64);
        #pragma unroll 4
        for (int i=tid; i<GPB*64/4; i+=THR){
            int lin = i*4;
            int gg  = lin>>6;
            int c0  = lin & 63;
            int hwl = (idx0+gg)/3 - hw0;
            d4[i] = *reinterpret_cast<const float4*>(&s_ft[hwl*FTS + c0]);
        }
        /* scales: gather from slots 1-3 */
        d4 = (float4*)(out + OFF_SCL + (size_t)g0*3);
        for (int i=tid; i<GPB*3/4; i+=THR){
            int lin=i*4; float vv[4];
            #pragma unroll
            for (int w=0;w<4;w++){
                int idx=lin+w, t=idx/3, j=idx-t*3;
                vv[w] = s_in[t*RST+1+j];
            }
            d4[i] = make_float4(vv[0],vv[1],vv[2],vv[3]);
        }
        /* rotations: aligned LDS128 from slot 4 */
        d4 = (float4*)(out + OFF_ROT + (size_t)g0*4);
        for (int i=tid; i<GPB; i+=THR){
            d4[i] = *reinterpret_cast<const float4*>(s_in + i*RST + 4);
        }
    }
}

/* ------------------------------------------------------------------ */
extern "C" void kernel_launch(void* const* d_in, const int* in_sizes, int n_in,
                              void* d_out, int out_size){
    const float* ext    = (const float*)d_in[0];
    const float* intr   = (const float*)d_in[1];
    const float* coords = (const float*)d_in[2];
    const float* depths = (const float*)d_in[3];
    const float* opac   = (const float*)d_in[4];
    const float* raw    = (const float*)d_in[5];
    const float* gf     = (const float*)d_in[6];
    const void*  ph     = (n_in > 7) ? d_in[7] : nullptr;
    const void*  pw     = (n_in > 8) ? d_in[8] : nullptr;
    float* out = (float*)d_out;

    setup_kernel<<<BB*5, 32>>>(ext, intr, ph, pw);

    size_t smem = (size_t)(GPB*RST + NHW*FTS + 165 + 24)*sizeof(float);
    cudaFuncSetAttribute(gauss_kernel, cudaFuncAttributeMaxDynamicSharedMemorySize, (int)smem);
    gauss_kernel<<<NG/GPB, THR, smem>>>(coords, depths, opac, raw, gf, out);
}